// round 7
// baseline (speedup 1.0000x reference)
#include <cuda_runtime.h>
#include <cstdint>
#include <math.h>

#define THREADS 256
#define TILE_ROWS 32
#define NF 128
#define NG 64
#define NM 3
#define CHUNKS 8
#define GPC 8
#define GRID 740          // 148 SMs x 5 resident blocks

#define HALF_LOG_2PI 0.9189385332046727f
#define L2E 1.4426950408889634f
#define LN2 0.6931471805599453f

__device__ float4 gPack[NG * 4];
__device__ int2   gIdx[NG];

__device__ __forceinline__ float ex2f(float x) {
    float y; asm("ex2.approx.ftz.f32 %0, %1;" : "=f"(y) : "f"(x)); return y;
}
__device__ __forceinline__ float lg2f(float x) {
    float y; asm("lg2.approx.ftz.f32 %0, %1;" : "=f"(y) : "f"(x)); return y;
}
__device__ __forceinline__ void cpasync4(uint32_t saddr, const float* gaddr) {
    asm volatile("cp.async.ca.shared.global [%0], [%1], 4;" :: "r"(saddr), "l"(gaddr));
}
__device__ __forceinline__ uint32_t smem_u32(const void* p) {
    uint32_t a;
    asm("{ .reg .u64 t; cvta.to.shared.u64 t, %1; cvt.u32.u64 %0, t; }" : "=r"(a) : "l"(p));
    return a;
}

// ---- Prep kernel: fold params (+ log-softmax) into per-group quadratic coeffs.
__global__ void spn_prep_kernel(const int* __restrict__ perm,
                                const float* __restrict__ means,
                                const float* __restrict__ stds,
                                const float* __restrict__ sumw)
{
    const int g = threadIdx.x;
    if (g >= NG) return;
    const int j0 = 2 * g, j1 = 2 * g + 1;
    gIdx[g] = make_int2(perm[j0], perm[j1]);

    float sw0 = sumw[g * 3 + 0];
    float sw1 = sumw[g * 3 + 1];
    float sw2 = sumw[g * 3 + 2];
    float mw  = fmaxf(sw0, fmaxf(sw1, sw2));
    float lse = mw + logf(expf(sw0 - mw) + expf(sw1 - mw) + expf(sw2 - mw));

    float C[3];
    #pragma unroll
    for (int m = 0; m < NM; ++m) {
        float mu0 = means[j0 * 3 + m], sd0 = stds[j0 * 3 + m];
        float mu1 = means[j1 * 3 + m], sd1 = stds[j1 * 3 + m];
        float is0 = 1.0f / sd0, is1 = 1.0f / sd1;
        float is0sq = is0 * is0, is1sq = is1 * is1;
        float a0 = -0.5f * is0sq, b0 = mu0 * is0sq;
        float c0 = -0.5f * mu0 * mu0 * is0sq - logf(sd0) - HALF_LOG_2PI;
        float a1 = -0.5f * is1sq, b1 = mu1 * is1sq;
        float c1 = -0.5f * mu1 * mu1 * is1sq - logf(sd1) - HALF_LOG_2PI;
        float logw = (m == 0 ? sw0 : (m == 1 ? sw1 : sw2)) - lse;
        C[m] = (c0 + c1 + logw) * L2E;
        gPack[g * 4 + m] = make_float4(a0 * L2E, b0 * L2E, a1 * L2E, b1 * L2E);
    }
    gPack[g * 4 + 3] = make_float4(C[0], C[1], C[2], 0.0f);
}

__global__ void __launch_bounds__(THREADS, 5)
spn_kernel(const float* __restrict__ x,
           float* __restrict__ out,
           int B)
{
    // Static smem: 4096 + 512 + 32768 + 1024 = 38400 B  (5 blocks/SM)
    __shared__ float4 sPack[NG * 4];
    __shared__ int2   sIdx[NG];
    __shared__ float  sx[2][TILE_ROWS * NF];     // XOR-swizzled, pitch 128
    __shared__ float  sRed[CHUNKS * TILE_ROWS];

    const int t = threadIdx.x;
    const int nTiles = (B + TILE_ROWS - 1) / TILE_ROWS;
    const long long totalElem = (long long)B * NF;

    // ---- coefficients into smem (once per block)
    sPack[t] = gPack[t];
    if (t < NG) sIdx[t] = gIdx[t];

    const uint32_t sxBase0 = smem_u32(&sx[0][0]);
    const uint32_t sxBase1 = smem_u32(&sx[1][0]);

    // Prefetch tile = blockIdx.x into buffer 0.
    {
        int tile0 = blockIdx.x;
        if (tile0 < nTiles) {
            long long gBase = (long long)tile0 * TILE_ROWS * NF;
            #pragma unroll
            for (int i = 0; i < 16; ++i) {
                int idx = t + i * THREADS;
                int r = idx >> 7, c = idx & 127;
                uint32_t sdst = sxBase0 + ((r << 7) + (c ^ r)) * 4;
                long long gi = gBase + idx;
                if (gi < totalElem) cpasync4(sdst, x + gi);
            }
        }
        asm volatile("cp.async.commit_group;");
    }

    const int chunk = t >> 5;     // warp id = group chunk
    const int lane  = t & 31;     // lane = row within tile
    const int gBaseG = chunk * GPC;

    int pb = 0;
    for (int tile = blockIdx.x; tile < nTiles; tile += GRID) {
        int nxt = tile + GRID;
        if (nxt < nTiles) {
            uint32_t sb = (pb ^ 1) ? sxBase1 : sxBase0;
            long long gBase = (long long)nxt * TILE_ROWS * NF;
            #pragma unroll
            for (int i = 0; i < 16; ++i) {
                int idx = t + i * THREADS;
                int r = idx >> 7, c = idx & 127;
                uint32_t sdst = sb + ((r << 7) + (c ^ r)) * 4;
                long long gi = gBase + idx;
                if (gi < totalElem) cpasync4(sdst, x + gi);
            }
            asm volatile("cp.async.commit_group;");
            asm volatile("cp.async.wait_group 1;");
        } else {
            asm volatile("cp.async.wait_group 0;");
        }
        __syncthreads();

        // ---- compute: warp handles its 8 groups for all 32 rows (lane = row)
        const float* xr = &sx[pb][lane * NF];
        const int lxor = lane;    // swizzle: element c at xr[c ^ lane]

        float accM = 0.0f, accL = 0.0f;

        // prime the per-iteration critical chain
        int2 uv = sIdx[gBaseG];
        float x0 = xr[uv.x ^ lxor];
        float x1 = xr[uv.y ^ lxor];

        #pragma unroll
        for (int i = 0; i < GPC; ++i) {
            const int gn = gBaseG + ((i + 1) & (GPC - 1));
            int2 nuv = sIdx[gn];
            float nx0 = xr[nuv.x ^ lxor];
            float nx1 = xr[nuv.y ^ lxor];

            const int g = gBaseG + i;
            float4 k0 = sPack[g * 4 + 0];
            float4 k1 = sPack[g * 4 + 1];
            float4 k2 = sPack[g * 4 + 2];
            float4 kc = sPack[g * 4 + 3];

            float p0 = fmaf(fmaf(k0.z, x1, k0.w), x1, fmaf(fmaf(k0.x, x0, k0.y), x0, kc.x));
            float p1 = fmaf(fmaf(k1.z, x1, k1.w), x1, fmaf(fmaf(k1.x, x0, k1.y), x0, kc.y));
            float p2 = fmaf(fmaf(k2.z, x1, k2.w), x1, fmaf(fmaf(k2.x, x0, k2.y), x0, kc.z));

            float mx = fmaxf(p0, fmaxf(p1, p2));
            float s  = ex2f(p0 - mx) + ex2f(p1 - mx) + ex2f(p2 - mx);
            accM += mx;
            accL += lg2f(s);

            x0 = nx0; x1 = nx1;
        }

        sRed[chunk * TILE_ROWS + lane] = accM + accL;
        __syncthreads();

        // ---- reduce 8 chunk partials per row; store
        if (t < TILE_ROWS) {
            float v = 0.0f;
            #pragma unroll
            for (int c = 0; c < CHUNKS; ++c)
                v += sRed[c * TILE_ROWS + t];
            int gRow = tile * TILE_ROWS + t;
            if (gRow < B) out[gRow] = v * LN2;
        }
        pb ^= 1;
    }
}

extern "C" void kernel_launch(void* const* d_in, const int* in_sizes, int n_in,
                              void* d_out, int out_size)
{
    const float* x     = (const float*)d_in[0];
    const int*   perm  = (const int*)d_in[1];
    const float* means = (const float*)d_in[2];
    const float* stds  = (const float*)d_in[3];
    const float* sumw  = (const float*)d_in[4];
    float* out = (float*)d_out;

    int B = in_sizes[0] / NF;

    spn_prep_kernel<<<1, 64>>>(perm, means, stds, sumw);
    spn_kernel<<<GRID, THREADS>>>(x, out, B);
}